// round 1
// baseline (speedup 1.0000x reference)
#include <cuda_runtime.h>
#include <cstdint>
#include <math.h>

// Problem constants (fixed shapes for this problem)
#define B_IMGS   8
#define N_PREDS  100
#define HW       25600
#define K_CLS    80
#define T_TGT    160
#define M_TGT    20
#define MROWS    800      // B_IMGS * N_PREDS

// GEMM tiling
#define BM      128
#define BK      32
#define NSPLIT  20
#define KCHUNK  1280      // HW / NSPLIT
#define KTILES  40        // KCHUNK / BK
#define APITCH  36
#define BPITCH  36
#define MTILES  7         // ceil(800/128)

// Scratch (no allocations allowed -> __device__ globals)
__device__ float g_partial[NSPLIT * MROWS * T_TGT];   // 10.24 MB split-K partials
__device__ float g_pnorm[NSPLIT * MROWS];
__device__ float g_tnorm[NSPLIT * T_TGT];
__device__ float g_cls[MROWS * K_CLS];

__device__ __forceinline__ void mma_tf32(float* c, uint32_t a0, uint32_t a1,
                                         uint32_t a2, uint32_t a3,
                                         uint32_t b0, uint32_t b1) {
    asm volatile(
        "mma.sync.aligned.m16n8k8.row.col.f32.tf32.tf32.f32 "
        "{%0,%1,%2,%3}, {%4,%5,%6,%7}, {%8,%9}, {%0,%1,%2,%3};\n"
        : "+f"(c[0]), "+f"(c[1]), "+f"(c[2]), "+f"(c[3])
        : "r"(a0), "r"(a1), "r"(a2), "r"(a3), "r"(b0), "r"(b1));
}

__device__ __forceinline__ uint32_t f32_to_tf32(float x) {
    uint32_t r;
    asm("cvt.rna.tf32.f32 %0, %1;" : "=r"(r) : "f"(x));
    return r;
}

// ---------------------------------------------------------------------------
// Split-K tf32 GEMM: partial[s][m][n] = sum_{k in chunk s} pm[m,k]*tm[n,k]
// Also emits per-chunk row sums-of-squares for pm (all tiles) and tm (mtile 0).
// ---------------------------------------------------------------------------
__global__ __launch_bounds__(256, 1)
void gemm_kernel(const float* __restrict__ pm, const float* __restrict__ tm) {
    __shared__ float As[BM * APITCH];     // [m][k], tf32-rounded
    __shared__ float Bs[T_TGT * BPITCH];  // [n][k], tf32-rounded

    const int tid   = threadIdx.x;
    const int lane  = tid & 31;
    const int wid   = tid >> 5;
    const int wm    = wid & 3;   // M quadrant: rows wm*32 .. +31
    const int wn    = wid >> 2;  // N half:    cols wn*80 .. +79
    const int mtile = blockIdx.x;
    const int s     = blockIdx.y;

    const int  m0 = mtile * BM;
    const long k0 = (long)s * KCHUNK;

    // staging mapping: 8 k-groups of 4 floats (float4), 32 row-slots
    const int g  = tid & 7;
    const int r8 = tid >> 3;

    float acc[2][10][4];
    #pragma unroll
    for (int a = 0; a < 2; a++)
        #pragma unroll
        for (int b = 0; b < 10; b++)
            #pragma unroll
            for (int c = 0; c < 4; c++) acc[a][b][c] = 0.f;

    float sqa[4] = {0.f, 0.f, 0.f, 0.f};
    float sqb[5] = {0.f, 0.f, 0.f, 0.f, 0.f};

    float4 regA[4], regB[5];

    // prefetch tile 0
    {
        long col = k0 + g * 4;
        #pragma unroll
        for (int i = 0; i < 4; i++) {
            int row = m0 + r8 + i * 32;
            regA[i] = (row < MROWS) ? *(const float4*)(pm + (long)row * HW + col)
                                    : make_float4(0.f, 0.f, 0.f, 0.f);
        }
        #pragma unroll
        for (int i = 0; i < 5; i++) {
            int row = r8 + i * 32;
            regB[i] = *(const float4*)(tm + (long)row * HW + col);
        }
    }

    for (int t = 0; t < KTILES; t++) {
        // sums-of-squares (true f32) + tf32 round + store to smem
        #pragma unroll
        for (int i = 0; i < 4; i++) {
            float4 v = regA[i];
            sqa[i] += v.x * v.x + v.y * v.y + v.z * v.z + v.w * v.w;
            float4 o;
            o.x = __uint_as_float(f32_to_tf32(v.x));
            o.y = __uint_as_float(f32_to_tf32(v.y));
            o.z = __uint_as_float(f32_to_tf32(v.z));
            o.w = __uint_as_float(f32_to_tf32(v.w));
            *(float4*)(As + (r8 + i * 32) * APITCH + g * 4) = o;
        }
        #pragma unroll
        for (int i = 0; i < 5; i++) {
            float4 v = regB[i];
            sqb[i] += v.x * v.x + v.y * v.y + v.z * v.z + v.w * v.w;
            float4 o;
            o.x = __uint_as_float(f32_to_tf32(v.x));
            o.y = __uint_as_float(f32_to_tf32(v.y));
            o.z = __uint_as_float(f32_to_tf32(v.z));
            o.w = __uint_as_float(f32_to_tf32(v.w));
            *(float4*)(Bs + (r8 + i * 32) * BPITCH + g * 4) = o;
        }
        __syncthreads();

        // issue next tile's global loads early (latency hidden by mma)
        if (t + 1 < KTILES) {
            long col = k0 + (long)(t + 1) * BK + g * 4;
            #pragma unroll
            for (int i = 0; i < 4; i++) {
                int row = m0 + r8 + i * 32;
                regA[i] = (row < MROWS) ? *(const float4*)(pm + (long)row * HW + col)
                                        : make_float4(0.f, 0.f, 0.f, 0.f);
            }
            #pragma unroll
            for (int i = 0; i < 5; i++) {
                int row = r8 + i * 32;
                regB[i] = *(const float4*)(tm + (long)row * HW + col);
            }
        }

        // compute: 4 k8-steps per 32-wide k tile
        #pragma unroll
        for (int k8 = 0; k8 < 4; k8++) {
            const int kk = k8 * 8;
            uint32_t bfr[10][2];
            #pragma unroll
            for (int nf = 0; nf < 10; nf++) {
                int n  = wn * 80 + nf * 8 + (lane >> 2);
                int kb = kk + (lane & 3);
                bfr[nf][0] = __float_as_uint(Bs[n * BPITCH + kb]);
                bfr[nf][1] = __float_as_uint(Bs[n * BPITCH + kb + 4]);
            }
            #pragma unroll
            for (int mf = 0; mf < 2; mf++) {
                int r  = wm * 32 + mf * 16 + (lane >> 2);
                int ka = kk + (lane & 3);
                uint32_t a0 = __float_as_uint(As[r * APITCH + ka]);
                uint32_t a1 = __float_as_uint(As[(r + 8) * APITCH + ka]);
                uint32_t a2 = __float_as_uint(As[r * APITCH + ka + 4]);
                uint32_t a3 = __float_as_uint(As[(r + 8) * APITCH + ka + 4]);
                #pragma unroll
                for (int nf = 0; nf < 10; nf++)
                    mma_tf32(acc[mf][nf], a0, a1, a2, a3, bfr[nf][0], bfr[nf][1]);
            }
        }
        __syncthreads();
    }

    // store split-K partials
    const long base = (long)s * MROWS * T_TGT;
    #pragma unroll
    for (int mf = 0; mf < 2; mf++) {
        #pragma unroll
        for (int nf = 0; nf < 10; nf++) {
            int mA = m0 + wm * 32 + mf * 16 + (lane >> 2);
            int mB = mA + 8;
            int n  = wn * 80 + nf * 8 + (lane & 3) * 2;
            if (mA < MROWS) {
                float2 v = make_float2(acc[mf][nf][0], acc[mf][nf][1]);
                *(float2*)&g_partial[base + (long)mA * T_TGT + n] = v;
            }
            if (mB < MROWS) {
                float2 v = make_float2(acc[mf][nf][2], acc[mf][nf][3]);
                *(float2*)&g_partial[base + (long)mB * T_TGT + n] = v;
            }
        }
    }

    // deterministic 8-lane tree reductions of row sums-of-squares
    #pragma unroll
    for (int i = 0; i < 4; i++) {
        float v = sqa[i];
        v += __shfl_down_sync(0xffffffffu, v, 1);
        v += __shfl_down_sync(0xffffffffu, v, 2);
        v += __shfl_down_sync(0xffffffffu, v, 4);
        int m = m0 + r8 + i * 32;
        if ((tid & 7) == 0 && m < MROWS) g_pnorm[s * MROWS + m] = v;
    }
    if (mtile == 0) {
        #pragma unroll
        for (int i = 0; i < 5; i++) {
            float v = sqb[i];
            v += __shfl_down_sync(0xffffffffu, v, 1);
            v += __shfl_down_sync(0xffffffffu, v, 2);
            v += __shfl_down_sync(0xffffffffu, v, 4);
            int tr = r8 + i * 32;
            if ((tid & 7) == 0) g_tnorm[s * T_TGT + tr] = v;
        }
    }
}

// ---------------------------------------------------------------------------
// Focal classification table: g_cls[m][k] = pos - neg
// ---------------------------------------------------------------------------
__global__ void focal_kernel(const float* __restrict__ logits) {
    int idx = blockIdx.x * blockDim.x + threadIdx.x;
    if (idx >= MROWS * K_CLS) return;
    float x  = logits[idx];
    float pl = 1.f / (1.f + expf(-x));
    float pos = 0.25f * (1.f - pl) * (1.f - pl) * (-logf(pl + 1e-8f));
    float neg = 0.75f * pl * pl * (-logf(1.f - pl + 1e-8f));
    g_cls[idx] = pos - neg;
}

// ---------------------------------------------------------------------------
// Epilogue: reduce split-K partials, dice score, add class cost, nan_to_num
// ---------------------------------------------------------------------------
__global__ void epilogue_kernel(const int* __restrict__ tgt_ids,
                                float* __restrict__ out) {
    int idx = blockIdx.x * blockDim.x + threadIdx.x;
    if (idx >= MROWS * T_TGT) return;
    int m = idx / T_TGT;
    int n = idx - m * T_TGT;
    float dot = 0.f, pn = 0.f, tn = 0.f;
    #pragma unroll
    for (int s = 0; s < NSPLIT; s++) {
        dot += g_partial[(long)s * MROWS * T_TGT + idx];
        pn  += g_pnorm[s * MROWS + m];
        tn  += g_tnorm[s * T_TGT + n];
    }
    float num = 2.f * dot;
    float den = pn + tn;
    float ms  = -((num + 1e-4f) / (den + 1e-4f));
    float cc  = g_cls[m * K_CLS + tgt_ids[n]];
    float c   = ms * 2.0f + cc * 1.0f;
    if (isnan(c) || isinf(c)) c = 0.f;
    out[idx] = c;
}

// ---------------------------------------------------------------------------
// 8 warp-parallel Jonker-Volgenant solvers (double precision), one per image.
// cost rows = targets (n=20), cols = preds (m=100);
// cost(t,p) = C[b, p, b*20 + t]. Outputs (pred asc, target) pairs.
// ---------------------------------------------------------------------------
__global__ __launch_bounds__(256, 1)
void lsa_kernel(const float* __restrict__ C,
                float* __restrict__ rows_out, float* __restrict__ cols_out) {
    __shared__ double u_sh[8][24];
    __shared__ int    p_sh[8][104];

    const int lane = threadIdx.x & 31;
    const int w    = threadIdx.x >> 5;  // image index
    const int n = M_TGT, m = N_PREDS;
    const double BIG = 1e18;

    const float* Cb = C + (long)w * N_PREDS * T_TGT + w * M_TGT; // cost = Cb[p*160 + t]

    double v[4], minv[4];
    int way[4];
    unsigned usedMask;

    #pragma unroll
    for (int sl = 0; sl < 4; sl++) v[sl] = 0.0;
    for (int jj = lane; jj < 104; jj += 32) p_sh[w][jj] = 0;
    if (lane < 24) u_sh[w][lane] = 0.0;
    __syncwarp();

    for (int i = 1; i <= n; i++) {
        if (lane == 0) p_sh[w][0] = i;
        #pragma unroll
        for (int sl = 0; sl < 4; sl++) { minv[sl] = BIG; way[sl] = 0; }
        usedMask = 0u;
        __syncwarp();

        int j0 = 0;
        while (true) {
            int slot0 = j0 >> 5, owner = j0 & 31;
            if (lane == owner) usedMask |= (1u << slot0);
            int i0 = p_sh[w][j0];
            double ui0 = u_sh[w][i0];

            // relax free columns
            #pragma unroll
            for (int sl = 0; sl < 4; sl++) {
                int j = lane + 32 * sl;
                if (j >= 1 && j <= m && !((usedMask >> sl) & 1u)) {
                    double cur = (double)Cb[(j - 1) * T_TGT + (i0 - 1)] - ui0 - v[sl];
                    if (cur < minv[sl]) { minv[sl] = cur; way[sl] = j0; }
                }
            }

            // argmin over free columns (tie -> smallest j, matching np.argmin)
            double bv = BIG;
            int bj = 0x7fffffff;
            #pragma unroll
            for (int sl = 0; sl < 4; sl++) {
                int j = lane + 32 * sl;
                if (j >= 1 && j <= m && !((usedMask >> sl) & 1u)) {
                    double mv = minv[sl];
                    if (mv < bv || (mv == bv && j < bj)) { bv = mv; bj = j; }
                }
            }
            #pragma unroll
            for (int off = 16; off; off >>= 1) {
                double ov = __shfl_xor_sync(0xffffffffu, bv, off);
                int    oj = __shfl_xor_sync(0xffffffffu, bj, off);
                if (ov < bv || (ov == bv && oj < bj)) { bv = ov; bj = oj; }
            }
            double delta = bv;
            int j1 = bj;

            // update potentials
            #pragma unroll
            for (int sl = 0; sl < 4; sl++) {
                int j = lane + 32 * sl;
                if (j <= m) {
                    if ((usedMask >> sl) & 1u) {
                        v[sl] -= delta;
                        u_sh[w][p_sh[w][j]] += delta;  // distinct rows -> race-free
                    } else {
                        minv[sl] -= delta;
                    }
                }
            }
            __syncwarp();

            j0 = j1;
            if (p_sh[w][j0] == 0) break;
        }

        // augment along alternating path
        while (j0 != 0) {
            int slot0 = j0 >> 5, owner = j0 & 31;
            int wsel = (slot0 == 0) ? way[0] : (slot0 == 1) ? way[1]
                     : (slot0 == 2) ? way[2] : way[3];
            int j1 = __shfl_sync(0xffffffffu, wsel, owner);
            if (lane == 0) p_sh[w][j0] = p_sh[w][j1];
            __syncwarp();
            j0 = j1;
        }
        __syncwarp();
    }

    if (lane == 0) {
        int cnt = 0;
        for (int j = 1; j <= m; j++) {
            int pj = p_sh[w][j];
            if (pj != 0) {
                rows_out[w * M_TGT + cnt] = (float)(j - 1);   // pred index (ascending)
                cols_out[w * M_TGT + cnt] = (float)(pj - 1);  // target index
                cnt++;
            }
        }
    }
}

// ---------------------------------------------------------------------------
extern "C" void kernel_launch(void* const* d_in, const int* in_sizes, int n_in,
                              void* d_out, int out_size) {
    const float* pm  = (const float*)d_in[0];  // pred_masks   (8,100,160,160)
    const float* pl  = (const float*)d_in[1];  // pred_logits  (8,100,80)
    const float* tm  = (const float*)d_in[2];  // target_masks (160,160,160)
    const int*   ids = (const int*)d_in[3];    // tgt_ids      (160,)
    float* out = (float*)d_out;                // [C | rows | cols] as f32

    gemm_kernel<<<dim3(MTILES, NSPLIT), 256>>>(pm, tm);
    focal_kernel<<<(MROWS * K_CLS + 255) / 256, 256>>>(pl);
    epilogue_kernel<<<(MROWS * T_TGT + 255) / 256, 256>>>(ids, out);
    lsa_kernel<<<1, 256>>>(out,
                           out + MROWS * T_TGT,
                           out + MROWS * T_TGT + B_IMGS * M_TGT);
}

// round 3
// speedup vs baseline: 1.0528x; 1.0528x over previous
#include <cuda_runtime.h>
#include <cstdint>
#include <math.h>

// Problem constants (fixed shapes for this problem)
#define B_IMGS   8
#define N_PREDS  100
#define HW       25600
#define K_CLS    80
#define T_TGT    160
#define M_TGT    20
#define MROWS    800      // B_IMGS * N_PREDS

// GEMM tiling
#define BM      128
#define BK      32
#define NSPLIT  20
#define KCHUNK  1280      // HW / NSPLIT
#define KTILES  40        // KCHUNK / BK
#define APITCH  36
#define BPITCH  36
#define MTILES  7         // ceil(800/128)

// Scratch (no allocations allowed -> __device__ globals)
__device__ float g_partial[NSPLIT * MROWS * T_TGT];   // 10.24 MB split-K partials
__device__ float g_pnorm[NSPLIT * MROWS];
__device__ float g_tnorm[NSPLIT * T_TGT];

__device__ __forceinline__ void mma_tf32(float* c, uint32_t a0, uint32_t a1,
                                         uint32_t a2, uint32_t a3,
                                         uint32_t b0, uint32_t b1) {
    asm volatile(
        "mma.sync.aligned.m16n8k8.row.col.f32.tf32.tf32.f32 "
        "{%0,%1,%2,%3}, {%4,%5,%6,%7}, {%8,%9}, {%0,%1,%2,%3};\n"
        : "+f"(c[0]), "+f"(c[1]), "+f"(c[2]), "+f"(c[3])
        : "r"(a0), "r"(a1), "r"(a2), "r"(a3), "r"(b0), "r"(b1));
}

__device__ __forceinline__ uint32_t f32_to_tf32(float x) {
    uint32_t r;
    asm("cvt.rna.tf32.f32 %0, %1;" : "=r"(r) : "f"(x));
    return r;
}

// ---------------------------------------------------------------------------
// Split-K tf32 GEMM: partial[s][m][n] = sum_{k in chunk s} pm[m,k]*tm[n,k]
// Also emits per-chunk row sums-of-squares for pm (all tiles) and tm (mtile 0).
// ---------------------------------------------------------------------------
__global__ __launch_bounds__(256, 1)
void gemm_kernel(const float* __restrict__ pm, const float* __restrict__ tm) {
    __shared__ float As[BM * APITCH];     // [m][k], tf32-rounded
    __shared__ float Bs[T_TGT * BPITCH];  // [n][k], tf32-rounded

    const int tid   = threadIdx.x;
    const int lane  = tid & 31;
    const int wid   = tid >> 5;
    const int wm    = wid & 3;   // M quadrant: rows wm*32 .. +31
    const int wn    = wid >> 2;  // N half:    cols wn*80 .. +79
    const int mtile = blockIdx.x;
    const int s     = blockIdx.y;

    const int  m0 = mtile * BM;
    const long k0 = (long)s * KCHUNK;

    // staging mapping: 8 k-groups of 4 floats (float4), 32 row-slots
    const int g  = tid & 7;
    const int r8 = tid >> 3;

    float acc[2][10][4];
    #pragma unroll
    for (int a = 0; a < 2; a++)
        #pragma unroll
        for (int b = 0; b < 10; b++)
            #pragma unroll
            for (int c = 0; c < 4; c++) acc[a][b][c] = 0.f;

    float sqa[4] = {0.f, 0.f, 0.f, 0.f};
    float sqb[5] = {0.f, 0.f, 0.f, 0.f, 0.f};

    float4 regA[4], regB[5];

    // prefetch tile 0
    {
        long col = k0 + g * 4;
        #pragma unroll
        for (int i = 0; i < 4; i++) {
            int row = m0 + r8 + i * 32;
            regA[i] = (row < MROWS) ? *(const float4*)(pm + (long)row * HW + col)
                                    : make_float4(0.f, 0.f, 0.f, 0.f);
        }
        #pragma unroll
        for (int i = 0; i < 5; i++) {
            int row = r8 + i * 32;
            regB[i] = *(const float4*)(tm + (long)row * HW + col);
        }
    }

    for (int t = 0; t < KTILES; t++) {
        // sums-of-squares (true f32) + tf32 round + store to smem
        #pragma unroll
        for (int i = 0; i < 4; i++) {
            float4 v = regA[i];
            sqa[i] += v.x * v.x + v.y * v.y + v.z * v.z + v.w * v.w;
            float4 o;
            o.x = __uint_as_float(f32_to_tf32(v.x));
            o.y = __uint_as_float(f32_to_tf32(v.y));
            o.z = __uint_as_float(f32_to_tf32(v.z));
            o.w = __uint_as_float(f32_to_tf32(v.w));
            *(float4*)(As + (r8 + i * 32) * APITCH + g * 4) = o;
        }
        #pragma unroll
        for (int i = 0; i < 5; i++) {
            float4 v = regB[i];
            sqb[i] += v.x * v.x + v.y * v.y + v.z * v.z + v.w * v.w;
            float4 o;
            o.x = __uint_as_float(f32_to_tf32(v.x));
            o.y = __uint_as_float(f32_to_tf32(v.y));
            o.z = __uint_as_float(f32_to_tf32(v.z));
            o.w = __uint_as_float(f32_to_tf32(v.w));
            *(float4*)(Bs + (r8 + i * 32) * BPITCH + g * 4) = o;
        }
        __syncthreads();

        // issue next tile's global loads early (latency hidden by mma)
        if (t + 1 < KTILES) {
            long col = k0 + (long)(t + 1) * BK + g * 4;
            #pragma unroll
            for (int i = 0; i < 4; i++) {
                int row = m0 + r8 + i * 32;
                regA[i] = (row < MROWS) ? *(const float4*)(pm + (long)row * HW + col)
                                        : make_float4(0.f, 0.f, 0.f, 0.f);
            }
            #pragma unroll
            for (int i = 0; i < 5; i++) {
                int row = r8 + i * 32;
                regB[i] = *(const float4*)(tm + (long)row * HW + col);
            }
        }

        // compute: 4 k8-steps per 32-wide k tile
        #pragma unroll
        for (int k8 = 0; k8 < 4; k8++) {
            const int kk = k8 * 8;
            uint32_t bfr[10][2];
            #pragma unroll
            for (int nf = 0; nf < 10; nf++) {
                int n  = wn * 80 + nf * 8 + (lane >> 2);
                int kb = kk + (lane & 3);
                bfr[nf][0] = __float_as_uint(Bs[n * BPITCH + kb]);
                bfr[nf][1] = __float_as_uint(Bs[n * BPITCH + kb + 4]);
            }
            #pragma unroll
            for (int mf = 0; mf < 2; mf++) {
                int r  = wm * 32 + mf * 16 + (lane >> 2);
                int ka = kk + (lane & 3);
                uint32_t a0 = __float_as_uint(As[r * APITCH + ka]);
                uint32_t a1 = __float_as_uint(As[(r + 8) * APITCH + ka]);
                uint32_t a2 = __float_as_uint(As[r * APITCH + ka + 4]);
                uint32_t a3 = __float_as_uint(As[(r + 8) * APITCH + ka + 4]);
                #pragma unroll
                for (int nf = 0; nf < 10; nf++)
                    mma_tf32(acc[mf][nf], a0, a1, a2, a3, bfr[nf][0], bfr[nf][1]);
            }
        }
        __syncthreads();
    }

    // store split-K partials
    const long base = (long)s * MROWS * T_TGT;
    #pragma unroll
    for (int mf = 0; mf < 2; mf++) {
        #pragma unroll
        for (int nf = 0; nf < 10; nf++) {
            int mA = m0 + wm * 32 + mf * 16 + (lane >> 2);
            int mB = mA + 8;
            int n  = wn * 80 + nf * 8 + (lane & 3) * 2;
            if (mA < MROWS) {
                float2 v = make_float2(acc[mf][nf][0], acc[mf][nf][1]);
                *(float2*)&g_partial[base + (long)mA * T_TGT + n] = v;
            }
            if (mB < MROWS) {
                float2 v = make_float2(acc[mf][nf][2], acc[mf][nf][3]);
                *(float2*)&g_partial[base + (long)mB * T_TGT + n] = v;
            }
        }
    }

    // deterministic 8-lane tree reductions of row sums-of-squares
    #pragma unroll
    for (int i = 0; i < 4; i++) {
        float v = sqa[i];
        v += __shfl_down_sync(0xffffffffu, v, 1);
        v += __shfl_down_sync(0xffffffffu, v, 2);
        v += __shfl_down_sync(0xffffffffu, v, 4);
        int m = m0 + r8 + i * 32;
        if ((tid & 7) == 0 && m < MROWS) g_pnorm[s * MROWS + m] = v;
    }
    if (mtile == 0) {
        #pragma unroll
        for (int i = 0; i < 5; i++) {
            float v = sqb[i];
            v += __shfl_down_sync(0xffffffffu, v, 1);
            v += __shfl_down_sync(0xffffffffu, v, 2);
            v += __shfl_down_sync(0xffffffffu, v, 4);
            int tr = r8 + i * 32;
            if ((tid & 7) == 0) g_tnorm[s * T_TGT + tr] = v;
        }
    }
}

// ---------------------------------------------------------------------------
// Epilogue: reduce split-K partials, dice score, focal class cost (inlined),
// nan_to_num.
// ---------------------------------------------------------------------------
__global__ void epilogue_kernel(const float* __restrict__ logits,
                                const int* __restrict__ tgt_ids,
                                float* __restrict__ out) {
    int idx = blockIdx.x * blockDim.x + threadIdx.x;
    if (idx >= MROWS * T_TGT) return;
    int m = idx / T_TGT;
    int n = idx - m * T_TGT;
    float dot = 0.f, pn = 0.f, tn = 0.f;
    #pragma unroll
    for (int s = 0; s < NSPLIT; s++) {
        dot += g_partial[(long)s * MROWS * T_TGT + idx];
        pn  += g_pnorm[s * MROWS + m];
        tn  += g_tnorm[s * T_TGT + n];
    }
    float num = 2.f * dot;
    float den = pn + tn;
    float ms  = -((num + 1e-4f) / (den + 1e-4f));

    // focal classification cost for (m, tgt_ids[n])
    float x  = logits[m * K_CLS + tgt_ids[n]];
    float pl = 1.f / (1.f + expf(-x));
    float pos = 0.25f * (1.f - pl) * (1.f - pl) * (-logf(pl + 1e-8f));
    float neg = 0.75f * pl * pl * (-logf(1.f - pl + 1e-8f));
    float cc  = pos - neg;

    float c = ms * 2.0f + cc * 1.0f;
    if (isnan(c) || isinf(c)) c = 0.f;
    out[idx] = c;
}

// ---------------------------------------------------------------------------
// 8 block-parallel Jonker-Volgenant solvers (double precision), one per image,
// one warp per block. Cost block is preloaded into SMEM so the serial Dijkstra
// chain runs at LDS latency instead of DRAM/L2 latency.
// cost rows = targets (n=20), cols = preds (m=100);
// cost(t,p) = C[b, p, b*20 + t]. Outputs (pred asc, target) pairs.
// ---------------------------------------------------------------------------
__global__ __launch_bounds__(32, 1)
void lsa_kernel(const float* __restrict__ C,
                float* __restrict__ rows_out, float* __restrict__ cols_out) {
    __shared__ float  cost_sh[M_TGT][104];  // [t][p], padded
    __shared__ double u_sh[24];
    __shared__ int    p_sh[104];

    const int lane = threadIdx.x;
    const int w    = blockIdx.x;  // image index
    const int n = M_TGT, m = N_PREDS;
    const double BIG = 1e18;

    const float* Cb = C + (long)w * N_PREDS * T_TGT + w * M_TGT; // cost = Cb[p*160 + t]

    // preload cost block into SMEM: cost_sh[t][p] = Cb[p*160 + t]
    for (int idx = lane; idx < N_PREDS * M_TGT; idx += 32) {
        int p = idx / M_TGT;
        int t = idx - p * M_TGT;
        cost_sh[t][p] = Cb[p * T_TGT + t];
    }
    for (int jj = lane; jj < 104; jj += 32) p_sh[jj] = 0;
    if (lane < 24) u_sh[lane] = 0.0;
    __syncwarp();

    double v[4], minv[4];
    int way[4];
    unsigned usedMask;

    #pragma unroll
    for (int sl = 0; sl < 4; sl++) v[sl] = 0.0;

    for (int i = 1; i <= n; i++) {
        if (lane == 0) p_sh[0] = i;
        #pragma unroll
        for (int sl = 0; sl < 4; sl++) { minv[sl] = BIG; way[sl] = 0; }
        usedMask = 0u;
        __syncwarp();

        int j0 = 0;
        while (true) {
            int slot0 = j0 >> 5, owner = j0 & 31;
            if (lane == owner) usedMask |= (1u << slot0);
            int i0 = p_sh[j0];
            double ui0 = u_sh[i0];

            // relax free columns (cost from SMEM)
            const float* crow = cost_sh[i0 - 1];
            #pragma unroll
            for (int sl = 0; sl < 4; sl++) {
                int j = lane + 32 * sl;
                if (j >= 1 && j <= m && !((usedMask >> sl) & 1u)) {
                    double cur = (double)crow[j - 1] - ui0 - v[sl];
                    if (cur < minv[sl]) { minv[sl] = cur; way[sl] = j0; }
                }
            }

            // argmin over free columns (tie -> smallest j, matching np.argmin)
            double bv = BIG;
            int bj = 0x7fffffff;
            #pragma unroll
            for (int sl = 0; sl < 4; sl++) {
                int j = lane + 32 * sl;
                if (j >= 1 && j <= m && !((usedMask >> sl) & 1u)) {
                    double mv = minv[sl];
                    if (mv < bv || (mv == bv && j < bj)) { bv = mv; bj = j; }
                }
            }
            #pragma unroll
            for (int off = 16; off; off >>= 1) {
                double ov = __shfl_xor_sync(0xffffffffu, bv, off);
                int    oj = __shfl_xor_sync(0xffffffffu, bj, off);
                if (ov < bv || (ov == bv && oj < bj)) { bv = ov; bj = oj; }
            }
            double delta = bv;
            int j1 = bj;

            // update potentials
            #pragma unroll
            for (int sl = 0; sl < 4; sl++) {
                int j = lane + 32 * sl;
                if (j <= m) {
                    if ((usedMask >> sl) & 1u) {
                        v[sl] -= delta;
                        u_sh[p_sh[j]] += delta;  // distinct rows -> race-free
                    } else {
                        minv[sl] -= delta;
                    }
                }
            }
            __syncwarp();

            j0 = j1;
            if (p_sh[j0] == 0) break;
        }

        // augment along alternating path
        while (j0 != 0) {
            int slot0 = j0 >> 5, owner = j0 & 31;
            int wsel = (slot0 == 0) ? way[0] : (slot0 == 1) ? way[1]
                     : (slot0 == 2) ? way[2] : way[3];
            int j1 = __shfl_sync(0xffffffffu, wsel, owner);
            if (lane == 0) p_sh[j0] = p_sh[j1];
            __syncwarp();
            j0 = j1;
        }
        __syncwarp();
    }

    if (lane == 0) {
        int cnt = 0;
        for (int j = 1; j <= m; j++) {
            int pj = p_sh[j];
            if (pj != 0) {
                rows_out[w * M_TGT + cnt] = (float)(j - 1);   // pred index (ascending)
                cols_out[w * M_TGT + cnt] = (float)(pj - 1);  // target index
                cnt++;
            }
        }
    }
}

// ---------------------------------------------------------------------------
extern "C" void kernel_launch(void* const* d_in, const int* in_sizes, int n_in,
                              void* d_out, int out_size) {
    const float* pm  = (const float*)d_in[0];  // pred_masks   (8,100,160,160)
    const float* pl  = (const float*)d_in[1];  // pred_logits  (8,100,80)
    const float* tm  = (const float*)d_in[2];  // target_masks (160,160,160)
    const int*   ids = (const int*)d_in[3];    // tgt_ids      (160,)
    float* out = (float*)d_out;                // [C | rows | cols] as f32

    gemm_kernel<<<dim3(MTILES, NSPLIT), 256>>>(pm, tm);
    epilogue_kernel<<<(MROWS * T_TGT + 255) / 256, 256>>>(pl, ids, out);
    lsa_kernel<<<B_IMGS, 32>>>(out,
                               out + MROWS * T_TGT,
                               out + MROWS * T_TGT + B_IMGS * M_TGT);
}